// round 1
// baseline (speedup 1.0000x reference)
#include <cuda_runtime.h>
#include <cstdint>

// Problem constants (fixed by the reference: x(32,256,56,56), w(256,256,3,3), bias(256))
#define NB    32
#define CIN   256
#define HH    56
#define WW    56
#define KOUT  256

// Tiling
#define BK     64      // output channels per block
#define BH     4       // output rows per block
#define BWT    28      // output cols per block
#define CCHUNK 16      // input channels per smem stage

// Per-thread microtile: 4 channels x 7 pixels, 256 threads = 16 (k-groups) x 16 (pixel-groups)

__global__ __launch_bounds__(256, 3)
void conv3x3_fp32_kernel(const float* __restrict__ x,
                         const float* __restrict__ wgt,
                         const float* __restrict__ bias,
                         float* __restrict__ out)
{
    // smem: input tile 16c x 6 x 30 (rows h0-1..h0+4, cols w0-1..w0+28)
    //       weights  144 (c*9+tap) x 64 k, XOR-swizzled in float4 groups
    __shared__ float s_in[CCHUNK][6][30];          // 11520 B
    __shared__ float s_w[CCHUNK * 9][64];          // 36864 B  (total 48384 <= 48KB)

    const int tid  = threadIdx.x;
    const int tile = blockIdx.x;          // 0..27 : (h-tile, w-tile)
    const int tw   = tile & 1;            // 0..1
    const int th   = tile >> 1;           // 0..13
    const int k0   = blockIdx.y * BK;     // 0,64,128,192
    const int n    = blockIdx.z;          // 0..31
    const int h0   = th * BH;
    const int w0   = tw * BWT;

    const int k_t   = tid & 15;           // which 4-channel group
    const int pix_t = tid >> 4;           // 0..15
    const int prow  = pix_t >> 2;         // 0..3  output row within tile
    const int cbase = (pix_t & 3) * 7;    // 0,7,14,21 output col base

    float acc[4][7];
    #pragma unroll
    for (int a = 0; a < 4; ++a)
        #pragma unroll
        for (int p = 0; p < 7; ++p)
            acc[a][p] = 0.0f;

    const float* xn = x + (size_t)n * CIN * HH * WW;

    #pragma unroll 1
    for (int cc = 0; cc < CIN / CCHUNK; ++cc) {
        const int c0 = cc * CCHUNK;
        __syncthreads();

        // ---- stage input tile: 16 x 6 x 30 = 2880 floats ----
        #pragma unroll 1
        for (int i = tid; i < CCHUNK * 6 * 30; i += 256) {
            const int col = i % 30;
            const int row = (i / 30) % 6;
            const int c   = i / 180;
            const int hin = h0 - 1 + row;
            const int win = w0 - 1 + col;
            float v = 0.0f;
            if ((unsigned)hin < HH && (unsigned)win < WW)
                v = xn[((size_t)(c0 + c) * HH + hin) * WW + win];
            s_in[c][row][col] = v;
        }

        // ---- stage weights: 64k x (16c*9tap) = 9216 floats ----
        // gmem layout w[k][c][tap]: contiguous (c,tap) runs of 144 per k -> coalesced.
        // smem layout s_w[ct][k] with float4 XOR swizzle on the k4 index.
        #pragma unroll 1
        for (int i = tid; i < CCHUNK * 9 * BK; i += 256) {
            const int ct = i % 144;           // c_local*9 + tap
            const int k  = i / 144;
            const float v = wgt[(size_t)(k0 + k) * (CIN * 9) + (size_t)c0 * 9 + ct];
            const int k4 = k >> 2;
            const int sw = (((k4 ^ (ct & 15)) << 2) | (k & 3));
            s_w[ct][sw] = v;
        }
        __syncthreads();

        // ---- compute: 16 input channels ----
        #pragma unroll 1
        for (int c = 0; c < CCHUNK; ++c) {
            #pragma unroll
            for (int kh = 0; kh < 3; ++kh) {
                float r[9];
                #pragma unroll
                for (int j = 0; j < 9; ++j)
                    r[j] = s_in[c][prow + kh][cbase + j];
                #pragma unroll
                for (int kw = 0; kw < 3; ++kw) {
                    const int ct = c * 9 + kh * 3 + kw;
                    const float4 w4 = *reinterpret_cast<const float4*>(
                        &s_w[ct][(k_t ^ (ct & 15)) << 2]);
                    #pragma unroll
                    for (int p = 0; p < 7; ++p) {
                        acc[0][p] += w4.x * r[p + kw];
                        acc[1][p] += w4.y * r[p + kw];
                        acc[2][p] += w4.z * r[p + kw];
                        acc[3][p] += w4.w * r[p + kw];
                    }
                }
            }
        }
    }

    // ---- epilogue: bias + store ----
    const int kk0 = k0 + (k_t << 2);
    const size_t obase = (size_t)n * KOUT * HH * WW;
    #pragma unroll
    for (int ch = 0; ch < 4; ++ch) {
        const int kk = kk0 + ch;
        const float b = bias[kk];
        float* op = out + obase + (size_t)kk * HH * WW
                        + (size_t)(h0 + prow) * WW + (w0 + cbase);
        #pragma unroll
        for (int p = 0; p < 7; ++p)
            op[p] = acc[ch][p] + b;
    }
}

extern "C" void kernel_launch(void* const* d_in, const int* in_sizes, int n_in,
                              void* d_out, int out_size)
{
    const float* x    = (const float*)d_in[0];
    const float* wgt  = (const float*)d_in[1];
    const float* bias = (const float*)d_in[2];
    float* out        = (float*)d_out;

    dim3 grid((HH / BH) * (WW / BWT),   // 14*2 = 28
              KOUT / BK,                // 4
              NB);                      // 32
    conv3x3_fp32_kernel<<<grid, 256>>>(x, wgt, bias, out);
}

// round 4
// speedup vs baseline: 3.3790x; 3.3790x over previous
#include <cuda_runtime.h>
#include <cuda_bf16.h>
#include <cstdint>

#define NB    32
#define CIN   256
#define HH    56
#define WW    56
#define KOUT  256
#define NPIX  (HH*WW)        // 3136
#define KDIM  (CIN*9)        // 2304
#define NCHUNK 36            // 2304 / 64 k-chunks

#define MTILE 128            // out channels per CTA
#define NTILE 112            // pixels per CTA (2 rows x 56)

// stage layout (bytes): A hi 128x128B, A lo, B hi 112x128B, B lo
#define AH_OFF 0
#define AL_OFF 16384
#define BH_OFF 32768
#define BL_OFF 47104
#define STAGE  61440
#define SM_DYN (2*STAGE + 128)

// ---------------- device scratch -------------------------------------------
__device__ __align__(16) __nv_bfloat16 g_whi[KOUT * KDIM];
__device__ __align__(16) __nv_bfloat16 g_wlo[KOUT * KDIM];
__device__ __align__(16) __nv_bfloat16 g_xhi[(size_t)NB * NPIX * CIN];
__device__ __align__(16) __nv_bfloat16 g_xlo[(size_t)NB * NPIX * CIN];

// ---------------- PTX helpers (sm_80-era, safe for sm_100 target) ----------
__device__ __forceinline__ uint32_t smem_u32(const void* p) {
    uint32_t a;
    asm("{ .reg .u64 t; cvta.to.shared.u64 t, %1; cvt.u32.u64 %0, t; }"
        : "=r"(a) : "l"(p));
    return a;
}

#define CP16(dst, src, sz) \
    asm volatile("cp.async.cg.shared.global [%0], [%1], 16, %2;" \
                 :: "r"(dst), "l"(src), "r"(sz) : "memory")
#define CP_COMMIT() asm volatile("cp.async.commit_group;" ::: "memory")
#define CP_WAIT1()  asm volatile("cp.async.wait_group 1;" ::: "memory")
#define CP_WAIT0()  asm volatile("cp.async.wait_group 0;" ::: "memory")

#define LDSM4(r, a) \
    asm volatile("ldmatrix.sync.aligned.m8n8.x4.shared.b16 {%0,%1,%2,%3}, [%4];" \
                 : "=r"((r)[0]),"=r"((r)[1]),"=r"((r)[2]),"=r"((r)[3]) : "r"(a))

#define MMA(d, a, b) \
    asm volatile("mma.sync.aligned.m16n8k16.row.col.f32.bf16.bf16.f32 " \
                 "{%0,%1,%2,%3}, {%4,%5,%6,%7}, {%8,%9}, {%0,%1,%2,%3};" \
                 : "+f"((d)[0]),"+f"((d)[1]),"+f"((d)[2]),"+f"((d)[3]) \
                 : "r"((a)[0]),"r"((a)[1]),"r"((a)[2]),"r"((a)[3]), \
                   "r"((b)[0]),"r"((b)[1]))

// ---------------- prepass 1: weights -> bf16 hi/lo, tap-major k order ------
__global__ void prepass_w(const float* __restrict__ w) {
    int i = blockIdx.x * 256 + threadIdx.x;
    if (i >= KOUT * KDIM) return;
    int k = i / KDIM, r = i % KDIM;
    int c = r / 9, tap = r % 9;
    float v = w[i];
    __nv_bfloat16 hi = __float2bfloat16(v);
    __nv_bfloat16 lo = __float2bfloat16(v - __bfloat162float(hi));
    int o = k * KDIM + tap * CIN + c;
    g_whi[o] = hi;
    g_wlo[o] = lo;
}

// ---------------- prepass 2: x NCHW fp32 -> NHWC bf16 hi/lo ----------------
__global__ void prepass_x(const float* __restrict__ x) {
    __shared__ float t[32][33];
    int n  = blockIdx.z;
    int p0 = blockIdx.x * 32;
    int c0 = blockIdx.y * 32;
    int tx = threadIdx.x, ty = threadIdx.y;   // 32 x 8

    const float* xb = x + ((size_t)n * CIN + c0) * NPIX + p0;
    #pragma unroll
    for (int yy = ty; yy < 32; yy += 8)
        t[yy][tx] = xb[(size_t)yy * NPIX + tx];
    __syncthreads();

    size_t ob = ((size_t)n * NPIX + p0) * CIN + c0;
    #pragma unroll
    for (int yy = ty; yy < 32; yy += 8) {
        float v = t[tx][yy];
        __nv_bfloat16 hi = __float2bfloat16(v);
        __nv_bfloat16 lo = __float2bfloat16(v - __bfloat162float(hi));
        g_xhi[ob + (size_t)yy * CIN + tx] = hi;
        g_xlo[ob + (size_t)yy * CIN + tx] = lo;
    }
}

// ---------------- main kernel ------------------------------------------------
__global__ __launch_bounds__(256, 1)
void conv_mma_kernel(const float* __restrict__ bias, float* __restrict__ out)
{
    extern __shared__ __align__(16) char dsm_raw[];

    const int tid = threadIdx.x;
    const int wid = tid >> 5;
    const int L   = tid & 31;
    const int wm  = wid & 3;             // M group (out-ch quarter)
    const int wn  = wid >> 2;            // N group (pixel row)

    const int r0 = blockIdx.x * 2;       // output row base
    const int k0 = blockIdx.y * MTILE;   // out-channel base
    const int n  = blockIdx.z;           // image

    uint32_t raw = smem_u32(dsm_raw);
    uint32_t sm  = (raw + 127u) & ~127u; // 128-aligned for swizzle

    // per-lane ldmatrix constants
    const int arowL = L & 15;            // A row within 16
    const int acb   = (L >> 4) << 4;     // A k-byte sub-offset (0/16)
    const int browL = wn * 56 + (L & 7); // B row base (n rows)
    const int bcb   = (L >> 3) << 4;     // B k-byte sub-offset (0/16/32/48)

    float acc[2][7][4];
    #pragma unroll
    for (int mi = 0; mi < 2; ++mi)
        #pragma unroll
        for (int ni = 0; ni < 7; ++ni)
            #pragma unroll
            for (int q = 0; q < 4; ++q)
                acc[mi][ni][q] = 0.0f;

    // ---- cp.async stage issue for chunk ch into buffer sb ----
    auto issue = [&](int ch, uint32_t sb) {
        const int tap = ch >> 2;
        const int c0  = (ch & 3) << 6;
        const int kh  = tap / 3 - 1;
        const int kw  = tap % 3 - 1;
        // B: 112 pixel rows x 8 vec16 (hi + lo)
        #pragma unroll 1
        for (int i = tid; i < NTILE * 8; i += 256) {
            const int p = i >> 3, v = i & 7;
            const int r = r0 + (p / 56) + kh;
            const int w = (p % 56) + kw;
            const bool in = ((unsigned)r < HH) & ((unsigned)w < WW);
            const size_t gi = in ?
                (((size_t)n * NPIX + (size_t)r * WW + w) * CIN + c0 + (v << 3)) : 0;
            uint32_t off = (uint32_t)(p << 7) + (v << 4);
            off ^= (off >> 3) & 0x70;
            const uint32_t sz = in ? 16u : 0u;
            CP16(sb + BH_OFF + off, g_xhi + gi, sz);
            CP16(sb + BL_OFF + off, g_xlo + gi, sz);
        }
        // A: 128 out-ch rows x 8 vec16 (hi + lo)
        #pragma unroll 1
        for (int i = tid; i < MTILE * 8; i += 256) {
            const int k = i >> 3, v = i & 7;
            const size_t gi = (size_t)(k0 + k) * KDIM + tap * CIN + c0 + (v << 3);
            uint32_t off = (uint32_t)(k << 7) + (v << 4);
            off ^= (off >> 3) & 0x70;
            CP16(sb + AH_OFF + off, g_whi + gi, 16u);
            CP16(sb + AL_OFF + off, g_wlo + gi, 16u);
        }
        CP_COMMIT();
    };

    // ---- compute on buffer sb ----
    auto compute = [&](uint32_t sb) {
        const uint32_t sAh = sb + AH_OFF, sAl = sb + AL_OFF;
        const uint32_t sBh = sb + BH_OFF, sBl = sb + BL_OFF;
        #pragma unroll
        for (int kp = 0; kp < 2; ++kp) {           // 32-k pairs
            uint32_t bh[7][4], bl[7][4];
            #pragma unroll
            for (int ni = 0; ni < 7; ++ni) {
                const int row = browL + ni * 8;
                const uint32_t ao = (uint32_t)(row << 7)
                                  + (((kp << 6) + bcb) ^ ((row & 7) << 4));
                LDSM4(bh[ni], sBh + ao);           // non-trans: k-contiguous rows
                LDSM4(bl[ni], sBl + ao);
            }
            #pragma unroll
            for (int ks = 0; ks < 2; ++ks) {       // 16-k steps
                uint32_t ah[2][4], al[2][4];
                #pragma unroll
                for (int mi = 0; mi < 2; ++mi) {
                    const int row = wm * 32 + mi * 16 + arowL;
                    const uint32_t ao = (uint32_t)(row << 7)
                                      + (((kp << 6) + (ks << 5) + acb) ^ ((row & 7) << 4));
                    LDSM4(ah[mi], sAh + ao);
                    LDSM4(al[mi], sAl + ao);
                }
                #pragma unroll
                for (int mi = 0; mi < 2; ++mi)
                    #pragma unroll
                    for (int ni = 0; ni < 7; ++ni) {
                        const uint32_t* ph = &bh[ni][ks * 2];
                        const uint32_t* pl = &bl[ni][ks * 2];
                        MMA(acc[mi][ni], ah[mi], ph);   // hi * hi
                        MMA(acc[mi][ni], ah[mi], pl);   // hi * lo
                        MMA(acc[mi][ni], al[mi], ph);   // lo * hi
                    }
            }
        }
    };

    // ---- pipelined main loop ----
    issue(0, sm);
    #pragma unroll 1
    for (int ch = 0; ch < NCHUNK; ++ch) {
        if (ch + 1 < NCHUNK) {
            issue(ch + 1, sm + ((ch + 1) & 1) * STAGE);
            CP_WAIT1();
        } else {
            CP_WAIT0();
        }
        __syncthreads();
        compute(sm + (ch & 1) * STAGE);
        __syncthreads();                 // guard before buffer reuse
    }

    // ---- epilogue: bias + store ----
    const int gID = L >> 2;              // 0..7
    const int tig = L & 3;               // 0..3
    const int r   = r0 + wn;
    float b0[2], b1[2];
    #pragma unroll
    for (int mi = 0; mi < 2; ++mi) {
        b0[mi] = bias[k0 + wm * 32 + mi * 16 + gID];
        b1[mi] = bias[k0 + wm * 32 + mi * 16 + gID + 8];
    }
    #pragma unroll
    for (int mi = 0; mi < 2; ++mi) {
        const int kbase = k0 + wm * 32 + mi * 16 + gID;
        float* o0 = out + (((size_t)n * KOUT + kbase)     * HH + r) * WW;
        float* o1 = out + (((size_t)n * KOUT + kbase + 8) * HH + r) * WW;
        #pragma unroll
        for (int ni = 0; ni < 7; ++ni) {
            const int c = ni * 8 + tig * 2;
            float2 v0 = make_float2(acc[mi][ni][0] + b0[mi], acc[mi][ni][1] + b0[mi]);
            float2 v1 = make_float2(acc[mi][ni][2] + b1[mi], acc[mi][ni][3] + b1[mi]);
            *reinterpret_cast<float2*>(o0 + c) = v0;
            *reinterpret_cast<float2*>(o1 + c) = v1;
        }
    }
}

// ---------------- launch -----------------------------------------------------
extern "C" void kernel_launch(void* const* d_in, const int* in_sizes, int n_in,
                              void* d_out, int out_size)
{
    const float* x    = (const float*)d_in[0];
    const float* wgt  = (const float*)d_in[1];
    const float* bias = (const float*)d_in[2];
    float* out        = (float*)d_out;

    cudaFuncSetAttribute(conv_mma_kernel,
                         cudaFuncAttributeMaxDynamicSharedMemorySize, SM_DYN);

    prepass_w<<<(KOUT * KDIM + 255) / 256, 256>>>(wgt);
    {
        dim3 g(NPIX / 32, CIN / 32, NB);
        dim3 b(32, 8);
        prepass_x<<<g, b>>>(x);
    }

    dim3 grid(HH / 2, KOUT / MTILE, NB);   // 28 x 2 x 32 = 1792 CTAs
    conv_mma_kernel<<<grid, 256, SM_DYN>>>(bias, out);
}

// round 5
// speedup vs baseline: 3.8314x; 1.1339x over previous
#include <cuda_runtime.h>
#include <cuda_bf16.h>
#include <cstdint>

#define NB    32
#define CIN   256
#define HH    56
#define WW    56
#define KOUT  256
#define NPIX  (HH*WW)        // 3136
#define KDIM  (CIN*9)        // 2304
#define NCHUNK 72            // 2304 / 32 k-chunks

#define MTILE 128            // out channels per CTA
#define NTILE 112            // pixels per CTA (2 rows x 56)

// stage layout (bytes), 64B rows: A hi 128x64, A lo, B hi 112x64, B lo
#define AH_OFF 0
#define AL_OFF 8192
#define BH_OFF 16384
#define BL_OFF 23552
#define STAGE  30720
#define SM_DYN (2*STAGE + 128)   // 61568 -> 2 CTAs/SM

// ---------------- device scratch -------------------------------------------
__device__ __align__(16) __nv_bfloat16 g_whi[KOUT * KDIM];
__device__ __align__(16) __nv_bfloat16 g_wlo[KOUT * KDIM];
__device__ __align__(16) __nv_bfloat16 g_xhi[(size_t)NB * NPIX * CIN];
__device__ __align__(16) __nv_bfloat16 g_xlo[(size_t)NB * NPIX * CIN];

// ---------------- PTX helpers ----------------------------------------------
__device__ __forceinline__ uint32_t smem_u32(const void* p) {
    uint32_t a;
    asm("{ .reg .u64 t; cvta.to.shared.u64 t, %1; cvt.u32.u64 %0, t; }"
        : "=r"(a) : "l"(p));
    return a;
}

#define CP16(dst, src, sz) \
    asm volatile("cp.async.cg.shared.global [%0], [%1], 16, %2;" \
                 :: "r"(dst), "l"(src), "r"(sz) : "memory")
#define CP_COMMIT() asm volatile("cp.async.commit_group;" ::: "memory")
#define CP_WAIT0()  asm volatile("cp.async.wait_group 0;" ::: "memory")

#define LDSM4(r, a) \
    asm volatile("ldmatrix.sync.aligned.m8n8.x4.shared.b16 {%0,%1,%2,%3}, [%4];" \
                 : "=r"((r)[0]),"=r"((r)[1]),"=r"((r)[2]),"=r"((r)[3]) : "r"(a))
#define LDSM2(r, a) \
    asm volatile("ldmatrix.sync.aligned.m8n8.x2.shared.b16 {%0,%1}, [%2];" \
                 : "=r"((r)[0]),"=r"((r)[1]) : "r"(a))

#define MMA(d, a, b) \
    asm volatile("mma.sync.aligned.m16n8k16.row.col.f32.bf16.bf16.f32 " \
                 "{%0,%1,%2,%3}, {%4,%5,%6,%7}, {%8,%9}, {%0,%1,%2,%3};" \
                 : "+f"((d)[0]),"+f"((d)[1]),"+f"((d)[2]),"+f"((d)[3]) \
                 : "r"((a)[0]),"r"((a)[1]),"r"((a)[2]),"r"((a)[3]), \
                   "r"((b)[0]),"r"((b)[1]))

// ---------------- fused prepass ---------------------------------------------
// z < NB: x NCHW fp32 -> NHWC bf16 hi/lo (32x32 tile transpose)
// z == NB: weights -> bf16 hi/lo, k-order tap*256+c
__global__ void prepass_all(const float* __restrict__ x,
                            const float* __restrict__ w) {
    __shared__ float t[32][33];
    const int tx = threadIdx.x, ty = threadIdx.y;   // 32 x 8

    if (blockIdx.z < NB) {
        const int n  = blockIdx.z;
        const int p0 = blockIdx.x * 32;
        const int c0 = blockIdx.y * 32;

        const float* xb = x + ((size_t)n * CIN + c0) * NPIX + p0;
        #pragma unroll
        for (int yy = ty; yy < 32; yy += 8)
            t[yy][tx] = xb[(size_t)yy * NPIX + tx];
        __syncthreads();

        size_t ob = ((size_t)n * NPIX + p0) * CIN + c0;
        #pragma unroll
        for (int yy = ty; yy < 32; yy += 8) {
            float v = t[tx][yy];
            __nv_bfloat16 hi = __float2bfloat16(v);
            __nv_bfloat16 lo = __float2bfloat16(v - __bfloat162float(hi));
            g_xhi[ob + (size_t)yy * CIN + tx] = hi;
            g_xlo[ob + (size_t)yy * CIN + tx] = lo;
        }
    } else {
        const int b = blockIdx.y * gridDim.x + blockIdx.x;   // 0..783
        const int tl = ty * 32 + tx;
        for (int i = b * 256 + tl; i < KOUT * KDIM; i += 784 * 256) {
            int k = i / KDIM, r = i % KDIM;
            int c = r / 9, tap = r % 9;
            float v = w[i];
            __nv_bfloat16 hi = __float2bfloat16(v);
            __nv_bfloat16 lo = __float2bfloat16(v - __bfloat162float(hi));
            int o = k * KDIM + tap * CIN + c;
            g_whi[o] = hi;
            g_wlo[o] = lo;
        }
    }
}

// ---------------- main kernel ------------------------------------------------
__global__ __launch_bounds__(256, 2)
void conv_mma_kernel(const float* __restrict__ bias, float* __restrict__ out)
{
    extern __shared__ __align__(16) char dsm_raw[];

    const int tid = threadIdx.x;
    const int wid = tid >> 5;
    const int L   = tid & 31;
    const int wm  = wid & 3;             // M group (out-ch quarter)
    const int wn  = wid >> 2;            // N group (pixel row)

    const int r0 = blockIdx.x * 2;       // output row base
    const int k0 = blockIdx.y * MTILE;   // out-channel base
    const int n  = blockIdx.z;           // image

    uint32_t raw = smem_u32(dsm_raw);
    uint32_t sm  = (raw + 127u) & ~127u;

    // per-lane ldmatrix constants
    const int arowL = L & 15;            // A row within 16
    const int akh   = L >> 4;            // A k-octet half (0/1)
    const int browL = wn * 56 + (L & 7); // B n-row base
    const int bkh   = (L >> 3) & 1;      // B k-octet half (0/1)

    float acc[2][7][4];
    #pragma unroll
    for (int mi = 0; mi < 2; ++mi)
        #pragma unroll
        for (int ni = 0; ni < 7; ++ni)
            #pragma unroll
            for (int q = 0; q < 4; ++q)
                acc[mi][ni][q] = 0.0f;

    // ---- cp.async stage issue for chunk ch (32 k) into buffer sb ----
    auto issue = [&](int ch, uint32_t sb) {
        const int tap = ch >> 3;
        const int c0  = (ch & 7) << 5;   // 0,32,...,224
        const int kh  = tap / 3 - 1;
        const int kw  = tap % 3 - 1;
        // B: 112 pixel rows x 4 vec16 (hi + lo each)
        #pragma unroll 1
        for (int i = tid; i < NTILE * 4; i += 256) {      // 1.75 iters
            const int p = i >> 2, v = i & 3;
            const int r = r0 + (p / 56) + kh;
            const int w = (p % 56) + kw;
            const bool in = ((unsigned)r < HH) & ((unsigned)w < WW);
            const size_t gi = in ?
                (((size_t)n * NPIX + (size_t)r * WW + w) * CIN + c0 + (v << 3)) : 0;
            uint32_t off = (uint32_t)(p << 6) + (v << 4);
            off ^= (off >> 3) & 0x30;                     // SW64
            const uint32_t sz = in ? 16u : 0u;
            CP16(sb + BH_OFF + off, g_xhi + gi, sz);
            CP16(sb + BL_OFF + off, g_xlo + gi, sz);
        }
        // A: 128 out-ch rows x 4 vec16 (hi + lo each)
        #pragma unroll 1
        for (int i = tid; i < MTILE * 4; i += 256) {      // 2 iters
            const int k = i >> 2, v = i & 3;
            const size_t gi = (size_t)(k0 + k) * KDIM + tap * CIN + c0 + (v << 3);
            uint32_t off = (uint32_t)(k << 6) + (v << 4);
            off ^= (off >> 3) & 0x30;
            CP16(sb + AH_OFF + off, g_whi + gi, 16u);
            CP16(sb + AL_OFF + off, g_wlo + gi, 16u);
        }
        CP_COMMIT();
    };

    // ---- compute chunk (32 k) on buffer sb ----
    auto compute = [&](uint32_t sb) {
        const uint32_t sAh = sb + AH_OFF, sAl = sb + AL_OFF;
        const uint32_t sBh = sb + BH_OFF, sBl = sb + BL_OFF;
        #pragma unroll
        for (int ks = 0; ks < 2; ++ks) {       // two 16-k steps
            uint32_t bh[7][2], bl[7][2];
            #pragma unroll
            for (int ni = 0; ni < 7; ++ni) {
                const int row = browL + ni * 8;
                const int c16 = (ks * 2 + bkh) ^ ((row >> 1) & 3);
                const uint32_t ao = (uint32_t)(row << 6) + (c16 << 4);
                LDSM2(bh[ni], sBh + ao);
                LDSM2(bl[ni], sBl + ao);
            }
            uint32_t ah[2][4], al[2][4];
            #pragma unroll
            for (int mi = 0; mi < 2; ++mi) {
                const int row = wm * 32 + mi * 16 + arowL;
                const int c16 = (ks * 2 + akh) ^ ((row >> 1) & 3);
                const uint32_t ao = (uint32_t)(row << 6) + (c16 << 4);
                LDSM4(ah[mi], sAh + ao);
                LDSM4(al[mi], sAl + ao);
            }
            #pragma unroll
            for (int mi = 0; mi < 2; ++mi)
                #pragma unroll
                for (int ni = 0; ni < 7; ++ni) {
                    MMA(acc[mi][ni], ah[mi], bh[ni]);   // hi * hi
                    MMA(acc[mi][ni], ah[mi], bl[ni]);   // hi * lo
                    MMA(acc[mi][ni], al[mi], bh[ni]);   // lo * hi
                }
        }
    };

    // ---- pipelined main loop: one sync per chunk ----
    issue(0, sm);
    #pragma unroll 1
    for (int ch = 0; ch < NCHUNK; ++ch) {
        CP_WAIT0();                    // chunk ch arrived (per-thread)
        __syncthreads();               // publish smem + guard buffer reuse
        if (ch + 1 < NCHUNK)
            issue(ch + 1, sm + ((ch + 1) & 1) * STAGE);  // overlaps compute
        compute(sm + (ch & 1) * STAGE);
    }

    // ---- epilogue: bias + store ----
    const int gID = L >> 2;              // 0..7
    const int tig = L & 3;               // 0..3
    const int r   = r0 + wn;
    #pragma unroll
    for (int mi = 0; mi < 2; ++mi) {
        const int kbase = k0 + wm * 32 + mi * 16 + gID;
        const float b0 = bias[kbase];
        const float b1 = bias[kbase + 8];
        float* o0 = out + (((size_t)n * KOUT + kbase)     * HH + r) * WW;
        float* o1 = out + (((size_t)n * KOUT + kbase + 8) * HH + r) * WW;
        #pragma unroll
        for (int ni = 0; ni < 7; ++ni) {
            const int c = ni * 8 + tig * 2;
            float2 v0 = make_float2(acc[mi][ni][0] + b0, acc[mi][ni][1] + b0);
            float2 v1 = make_float2(acc[mi][ni][2] + b1, acc[mi][ni][3] + b1);
            *reinterpret_cast<float2*>(o0 + c) = v0;
            *reinterpret_cast<float2*>(o1 + c) = v1;
        }
    }
}

// ---------------- launch -----------------------------------------------------
extern "C" void kernel_launch(void* const* d_in, const int* in_sizes, int n_in,
                              void* d_out, int out_size)
{
    const float* x    = (const float*)d_in[0];
    const float* wgt  = (const float*)d_in[1];
    const float* bias = (const float*)d_in[2];
    float* out        = (float*)d_out;

    cudaFuncSetAttribute(conv_mma_kernel,
                         cudaFuncAttributeMaxDynamicSharedMemorySize, SM_DYN);

    {
        dim3 g(NPIX / 32, CIN / 32, NB + 1);   // 98 x 8 x 33 (z=32: weights)
        dim3 b(32, 8);
        prepass_all<<<g, b>>>(x, wgt);
    }

    dim3 grid(HH / 2, KOUT / MTILE, NB);   // 28 x 2 x 32 = 1792 CTAs
    conv_mma_kernel<<<grid, 256, SM_DYN>>>(bias, out);
}

// round 6
// speedup vs baseline: 4.0966x; 1.0692x over previous
#include <cuda_runtime.h>
#include <cuda_bf16.h>
#include <cstdint>

#define NB    32
#define CIN   256
#define HH    56
#define WW    56
#define KOUT  256
#define NPIX  (HH*WW)        // 3136
#define KDIM  (CIN*9)        // 2304
#define NCHUNK 72            // 2304 / 32 k-chunks

#define MTILE 128            // out channels per CTA
#define NTILE 112            // pixels per CTA (2 rows x 56)

// stage layout (bytes), 64B rows: A hi 128x64, A lo, B hi 112x64, B lo
#define AH_OFF 0
#define AL_OFF 8192
#define BH_OFF 16384
#define BL_OFF 23552
#define STAGE  30720
#define SM_DYN (3*STAGE + 128)   // 92288/CTA -> 2 CTAs/SM (184.6KB of 228KB)

// ---------------- device scratch -------------------------------------------
__device__ __align__(16) __nv_bfloat16 g_whi[KOUT * KDIM];
__device__ __align__(16) __nv_bfloat16 g_wlo[KOUT * KDIM];
__device__ __align__(16) __nv_bfloat16 g_xhi[(size_t)NB * NPIX * CIN];
__device__ __align__(16) __nv_bfloat16 g_xlo[(size_t)NB * NPIX * CIN];

// ---------------- PTX helpers ----------------------------------------------
__device__ __forceinline__ uint32_t smem_u32(const void* p) {
    uint32_t a;
    asm("{ .reg .u64 t; cvta.to.shared.u64 t, %1; cvt.u32.u64 %0, t; }"
        : "=r"(a) : "l"(p));
    return a;
}

#define CP16(dst, src, sz) \
    asm volatile("cp.async.cg.shared.global [%0], [%1], 16, %2;" \
                 :: "r"(dst), "l"(src), "r"(sz) : "memory")
#define CP_COMMIT() asm volatile("cp.async.commit_group;" ::: "memory")
#define CP_WAIT1()  asm volatile("cp.async.wait_group 1;" ::: "memory")
#define CP_WAIT0()  asm volatile("cp.async.wait_group 0;" ::: "memory")

#define LDSM4(r, a) \
    asm volatile("ldmatrix.sync.aligned.m8n8.x4.shared.b16 {%0,%1,%2,%3}, [%4];" \
                 : "=r"((r)[0]),"=r"((r)[1]),"=r"((r)[2]),"=r"((r)[3]) : "r"(a))
#define LDSM2(r, a) \
    asm volatile("ldmatrix.sync.aligned.m8n8.x2.shared.b16 {%0,%1}, [%2];" \
                 : "=r"((r)[0]),"=r"((r)[1]) : "r"(a))

#define MMA(d, a, b) \
    asm volatile("mma.sync.aligned.m16n8k16.row.col.f32.bf16.bf16.f32 " \
                 "{%0,%1,%2,%3}, {%4,%5,%6,%7}, {%8,%9}, {%0,%1,%2,%3};" \
                 : "+f"((d)[0]),"+f"((d)[1]),"+f"((d)[2]),"+f"((d)[3]) \
                 : "r"((a)[0]),"r"((a)[1]),"r"((a)[2]),"r"((a)[3]), \
                   "r"((b)[0]),"r"((b)[1]))

// ---------------- fused prepass ---------------------------------------------
__global__ void prepass_all(const float* __restrict__ x,
                            const float* __restrict__ w) {
    __shared__ float t[32][33];
    const int tx = threadIdx.x, ty = threadIdx.y;   // 32 x 8

    if (blockIdx.z < NB) {
        const int n  = blockIdx.z;
        const int p0 = blockIdx.x * 32;
        const int c0 = blockIdx.y * 32;

        const float* xb = x + ((size_t)n * CIN + c0) * NPIX + p0;
        #pragma unroll
        for (int yy = ty; yy < 32; yy += 8)
            t[yy][tx] = xb[(size_t)yy * NPIX + tx];
        __syncthreads();

        size_t ob = ((size_t)n * NPIX + p0) * CIN + c0;
        #pragma unroll
        for (int yy = ty; yy < 32; yy += 8) {
            float v = t[tx][yy];
            __nv_bfloat16 hi = __float2bfloat16(v);
            __nv_bfloat16 lo = __float2bfloat16(v - __bfloat162float(hi));
            g_xhi[ob + (size_t)yy * CIN + tx] = hi;
            g_xlo[ob + (size_t)yy * CIN + tx] = lo;
        }
    } else {
        const int b = blockIdx.y * gridDim.x + blockIdx.x;   // 0..783
        const int tl = ty * 32 + tx;
        for (int i = b * 256 + tl; i < KOUT * KDIM; i += 784 * 256) {
            int k = i / KDIM, r = i % KDIM;
            int c = r / 9, tap = r % 9;
            float v = w[i];
            __nv_bfloat16 hi = __float2bfloat16(v);
            __nv_bfloat16 lo = __float2bfloat16(v - __bfloat162float(hi));
            int o = k * KDIM + tap * CIN + c;
            g_whi[o] = hi;
            g_wlo[o] = lo;
        }
    }
}

// ---------------- main kernel ------------------------------------------------
__global__ __launch_bounds__(256, 2)
void conv_mma_kernel(const float* __restrict__ bias, float* __restrict__ out)
{
    extern __shared__ __align__(16) char dsm_raw[];

    const int tid = threadIdx.x;
    const int wid = tid >> 5;
    const int L   = tid & 31;
    const int wm  = wid & 3;             // M group (out-ch quarter)
    const int wn  = wid >> 2;            // N group (pixel row)

    const int r0 = blockIdx.x * 2;       // output row base
    const int k0 = blockIdx.y * MTILE;   // out-channel base
    const int n  = blockIdx.z;           // image

    uint32_t raw = smem_u32(dsm_raw);
    uint32_t sm  = (raw + 127u) & ~127u;

    // per-lane ldmatrix constants
    const int arowL = L & 15;            // A row within 16
    const int akh   = L >> 4;            // A k-octet half (0/1)
    const int j4    = L >> 3;            // x4 matrix index (0..3)
    // B pair-load lane row: pi*16 + (j4>>1)*8 + (L&7), col sel j4&1
    const int bprow = wn * 56 + ((j4 >> 1) << 3) + (L & 7);
    const int bpcol = j4 & 1;
    // B leftover (ni=6) LDSM2 lane row
    const int bsrow = wn * 56 + 48 + (L & 7);
    const int bscol = j4 & 1;

    float acc[2][7][4];
    #pragma unroll
    for (int mi = 0; mi < 2; ++mi)
        #pragma unroll
        for (int ni = 0; ni < 7; ++ni)
            #pragma unroll
            for (int q = 0; q < 4; ++q)
                acc[mi][ni][q] = 0.0f;

    // ---- cp.async stage issue for chunk ch (32 k) into buffer sb ----
    auto issue = [&](int ch, uint32_t sb) {
        const int tap = ch >> 3;
        const int c0  = (ch & 7) << 5;   // 0,32,...,224
        const int kh  = tap / 3 - 1;
        const int kw  = tap % 3 - 1;
        // B: 112 pixel rows x 4 vec16 (hi + lo each)
        #pragma unroll 1
        for (int i = tid; i < NTILE * 4; i += 256) {
            const int p = i >> 2, v = i & 3;
            const int r = r0 + (p / 56) + kh;
            const int w = (p % 56) + kw;
            const bool in = ((unsigned)r < HH) & ((unsigned)w < WW);
            const size_t gi = in ?
                (((size_t)n * NPIX + (size_t)r * WW + w) * CIN + c0 + (v << 3)) : 0;
            uint32_t off = (uint32_t)(p << 6) + (v << 4);
            off ^= (off >> 3) & 0x30;                     // SW64
            const uint32_t sz = in ? 16u : 0u;
            CP16(sb + BH_OFF + off, g_xhi + gi, sz);
            CP16(sb + BL_OFF + off, g_xlo + gi, sz);
        }
        // A: 128 out-ch rows x 4 vec16 (hi + lo each)
        #pragma unroll 1
        for (int i = tid; i < MTILE * 4; i += 256) {
            const int k = i >> 2, v = i & 3;
            const size_t gi = (size_t)(k0 + k) * KDIM + tap * CIN + c0 + (v << 3);
            uint32_t off = (uint32_t)(k << 6) + (v << 4);
            off ^= (off >> 3) & 0x30;
            CP16(sb + AH_OFF + off, g_whi + gi, 16u);
            CP16(sb + AL_OFF + off, g_wlo + gi, 16u);
        }
        CP_COMMIT();
    };

    // ---- compute chunk (32 k) on buffer sb ----
    auto compute = [&](uint32_t sb) {
        const uint32_t sAh = sb + AH_OFF, sAl = sb + AL_OFF;
        const uint32_t sBh = sb + BH_OFF, sBl = sb + BL_OFF;
        #pragma unroll
        for (int ks = 0; ks < 2; ++ks) {       // two 16-k steps
            uint32_t bh[7][2], bl[7][2];
            // 3 pair-loads (ni = 0..5), x4: mats {ni,c0},{ni,c1},{ni+1,c0},{ni+1,c1}
            #pragma unroll
            for (int pi = 0; pi < 3; ++pi) {
                const int row = bprow + pi * 16;
                const int c16 = (ks * 2 + bpcol) ^ ((row >> 1) & 3);
                const uint32_t ao = (uint32_t)(row << 6) + (c16 << 4);
                LDSM4(&bh[pi * 2][0], sBh + ao);
                LDSM4(&bl[pi * 2][0], sBl + ao);
            }
            {   // leftover ni = 6
                const int c16 = (ks * 2 + bscol) ^ ((bsrow >> 1) & 3);
                const uint32_t ao = (uint32_t)(bsrow << 6) + (c16 << 4);
                LDSM2(bh[6], sBh + ao);
                LDSM2(bl[6], sBl + ao);
            }
            uint32_t ah[2][4], al[2][4];
            #pragma unroll
            for (int mi = 0; mi < 2; ++mi) {
                const int row = wm * 32 + mi * 16 + arowL;
                const int c16 = (ks * 2 + akh) ^ ((row >> 1) & 3);
                const uint32_t ao = (uint32_t)(row << 6) + (c16 << 4);
                LDSM4(ah[mi], sAh + ao);
                LDSM4(al[mi], sAl + ao);
            }
            #pragma unroll
            for (int mi = 0; mi < 2; ++mi)
                #pragma unroll
                for (int ni = 0; ni < 7; ++ni) {
                    MMA(acc[mi][ni], ah[mi], bh[ni]);   // hi * hi
                    MMA(acc[mi][ni], ah[mi], bl[ni]);   // hi * lo
                    MMA(acc[mi][ni], al[mi], bh[ni]);   // lo * hi
                }
        }
    };

    // ---- 3-stage pipelined main loop ----
    uint32_t bufs[3] = { sm, sm + STAGE, sm + 2 * STAGE };
    issue(0, bufs[0]);
    issue(1, bufs[1]);
    int rd = 0, wr = 2;
    #pragma unroll 1
    for (int ch = 0; ch < NCHUNK; ++ch) {
        if (ch + 1 < NCHUNK) CP_WAIT1();   // chunk ch arrived, ch+1 may fly
        else                 CP_WAIT0();
        __syncthreads();                   // publish + guard buffer reuse
        if (ch + 2 < NCHUNK) issue(ch + 2, bufs[wr]);
        compute(bufs[rd]);
        rd = (rd == 2) ? 0 : rd + 1;
        wr = (wr == 2) ? 0 : wr + 1;
    }

    // ---- epilogue: bias + store ----
    const int gID = L >> 2;              // 0..7
    const int tig = L & 3;               // 0..3
    const int r   = r0 + wn;
    #pragma unroll
    for (int mi = 0; mi < 2; ++mi) {
        const int kbase = k0 + wm * 32 + mi * 16 + gID;
        const float b0 = bias[kbase];
        const float b1 = bias[kbase + 8];
        float* o0 = out + (((size_t)n * KOUT + kbase)     * HH + r) * WW;
        float* o1 = out + (((size_t)n * KOUT + kbase + 8) * HH + r) * WW;
        #pragma unroll
        for (int ni = 0; ni < 7; ++ni) {
            const int c = ni * 8 + tig * 2;
            float2 v0 = make_float2(acc[mi][ni][0] + b0, acc[mi][ni][1] + b0);
            float2 v1 = make_float2(acc[mi][ni][2] + b1, acc[mi][ni][3] + b1);
            *reinterpret_cast<float2*>(o0 + c) = v0;
            *reinterpret_cast<float2*>(o1 + c) = v1;
        }
    }
}

// ---------------- launch -----------------------------------------------------
extern "C" void kernel_launch(void* const* d_in, const int* in_sizes, int n_in,
                              void* d_out, int out_size)
{
    const float* x    = (const float*)d_in[0];
    const float* wgt  = (const float*)d_in[1];
    const float* bias = (const float*)d_in[2];
    float* out        = (float*)d_out;

    cudaFuncSetAttribute(conv_mma_kernel,
                         cudaFuncAttributeMaxDynamicSharedMemorySize, SM_DYN);

    {
        dim3 g(NPIX / 32, CIN / 32, NB + 1);   // 98 x 8 x 33 (z=32: weights)
        dim3 b(32, 8);
        prepass_all<<<g, b>>>(x, wgt);
    }

    dim3 grid(HH / 2, KOUT / MTILE, NB);   // 28 x 2 x 32 = 1792 CTAs
    conv_mma_kernel<<<grid, 256, SM_DYN>>>(bias, out);
}